// round 13
// baseline (speedup 1.0000x reference)
#include <cuda_runtime.h>
#include <cuda_bf16.h>
#include <cstdint>

// Fixed shape: B=1, N=768, C_IN=C_OUT=16, R=8
#define NPTS   768
#define NTILES 384          // M-tiles of 16 rows (2 a's x 8 r); one CTA each
#define NTHR   256
#define NKS    48           // total ksteps (K=768 / 16)

typedef unsigned int u32;

// Built by conv_prep (all CTA-invariant):
__device__ uint4 g_bfragH[NKS * 32];     // B frags, mma-register order
__device__ uint4 g_bfragL[NKS * 32];
__device__ float g_dist[NPTS * NPTS];    // d[a][b], +EPS, sqrt'ed (2.36 MB)

__device__ __forceinline__ u32 pack_bf16x2(float lo, float hi) {
    u32 d;
    asm("cvt.rn.bf16x2.f32 %0, %1, %2;" : "=r"(d) : "f"(hi), "f"(lo));
    return d;
}
__device__ __forceinline__ float ex2f(float x) {
    float e;
    asm("ex2.approx.f32 %0, %1;" : "=f"(e) : "f"(x));
    return e;
}
__device__ __forceinline__ float sqrt_apx(float x) {
    float s;
    asm("sqrt.approx.f32 %0, %1;" : "=f"(s) : "f"(x));
    return s;
}
// D(16x8,f32) += A(16x16,row,bf16) * B(16x8,col,bf16)
__device__ __forceinline__ void mma16816(float& c0, float& c1, float& c2, float& c3,
                                         u32 a0, u32 a1, u32 a2, u32 a3,
                                         u32 b0, u32 b1) {
    asm("mma.sync.aligned.m16n8k16.row.col.f32.bf16.bf16.f32 "
        "{%0,%1,%2,%3}, {%4,%5,%6,%7}, {%8,%9}, {%0,%1,%2,%3};"
        : "+f"(c0), "+f"(c1), "+f"(c2), "+f"(c3)
        : "r"(a0), "r"(a1), "r"(a2), "r"(a3), "r"(b0), "r"(b1));
}

// ---------------------------------------------------------------------------
// Prep: blocks 0-5 build B fragments; blocks 6-293 build the distance table.
// Wide and parallel; runs under/before conv_main via PDL.
// ---------------------------------------------------------------------------
__global__ void __launch_bounds__(NTHR) conv_prep(const float* __restrict__ feat,
                                                  const float* __restrict__ geom)
{
    const int tid = threadIdx.x;

    if (blockIdx.x < 6) {
        // ---- B fragments in mma-register order ----
        const int idx  = blockIdx.x * NTHR + tid;         // 0..1535
        const int ks   = idx >> 5;
        const int lane = idx & 31;
        const int g    = lane >> 2;
        const int k0   = ks * 16 + (lane & 3) * 2;

        float f[8];
        #pragma unroll
        for (int q = 0; q < 2; q++) {                     // q=0: col g, q=1: col g+8
            const int j = g + q * 8;
            f[q * 4 + 0] = __ldg(&feat[(k0)     * 16 + j]);
            f[q * 4 + 1] = __ldg(&feat[(k0 + 1) * 16 + j]);
            f[q * 4 + 2] = __ldg(&feat[(k0 + 8) * 16 + j]);
            f[q * 4 + 3] = __ldg(&feat[(k0 + 9) * 16 + j]);
        }
        float h[8], l[8];
        #pragma unroll
        for (int q = 0; q < 8; q++) {
            h[q] = __bfloat162float(__float2bfloat16(f[q]));
            l[q] = f[q] - h[q];
        }
        uint4 BH, BL;
        BH.x = pack_bf16x2(h[0], h[1]);  BH.y = pack_bf16x2(h[2], h[3]);
        BH.z = pack_bf16x2(h[4], h[5]);  BH.w = pack_bf16x2(h[6], h[7]);
        BL.x = pack_bf16x2(l[0], l[1]);  BL.y = pack_bf16x2(l[2], l[3]);
        BL.z = pack_bf16x2(l[4], l[5]);  BL.w = pack_bf16x2(l[6], l[7]);
        g_bfragH[ks * 32 + lane] = BH;
        g_bfragL[ks * 32 + lane] = BL;
        return;
    }

    // ---- distance table: thread = (a, 8 consecutive b's) ----
    const int idx = (blockIdx.x - 6) * NTHR + tid;        // 0..73727
    const int a   = idx / 96;
    const int b8  = (idx % 96) * 8;

    const float ax = __ldg(&geom[a * 3]);
    const float ay = __ldg(&geom[a * 3 + 1]);
    const float az = __ldg(&geom[a * 3 + 2]);

    // 24 consecutive floats = geometry of b8..b8+7 (float4-aligned: 24*i % 4 == 0)
    float gb[24];
    const float4* gv = (const float4*)(geom + b8 * 3);
    #pragma unroll
    for (int q = 0; q < 6; q++) {
        const float4 v = __ldg(gv + q);
        gb[q * 4] = v.x; gb[q * 4 + 1] = v.y; gb[q * 4 + 2] = v.z; gb[q * 4 + 3] = v.w;
    }

    float d[8];
    #pragma unroll
    for (int q = 0; q < 8; q++) {
        const float dx = gb[q * 3]     - ax;
        const float dy = gb[q * 3 + 1] - ay;
        const float dz = gb[q * 3 + 2] - az;
        float d2 = fmaf(dx, dx, 1e-9f);
        d2 = fmaf(dy, dy, d2);
        d2 = fmaf(dz, dz, d2);
        d[q] = sqrt_apx(d2);
    }
    float4* dst = (float4*)(g_dist + a * NPTS + b8);
    dst[0] = make_float4(d[0], d[1], d[2], d[3]);
    dst[1] = make_float4(d[4], d[5], d[6], d[7]);
}

// ---------------------------------------------------------------------------
// Main (R10 topology, prologue removed):
//   CTA = M-tile of 16 rows (2 a's x 8 r); warp w covers K [w*96, w*96+96)
//   in 6 ksteps. Distances come from g_dist via broadcast LDG.64 (4 distinct
//   8B addresses per warp per vector). No distance prologue, no sD barrier.
// ---------------------------------------------------------------------------
__global__ void __launch_bounds__(NTHR, 4) conv_main(
    const float* __restrict__ W,       // [8,16,16]
    const float* __restrict__ mu,      // [8]
    const float* __restrict__ gamma,   // [8]
    float scale,
    float* __restrict__ out)           // [768,16]
{
    __shared__ float sRed[8 * 256];    // per-warp C tiles [w][row][col]
    __shared__ float sG[256];          // reduced G [row][col]

    const int tid  = threadIdx.x;
    const int lane = tid & 31;
    const int warp = tid >> 5;
    const int a0   = blockIdx.x * 2;

    const int g = lane >> 2;           // fragment group = r
    const int c = (lane & 3) * 2;

    // RBF consts (inputs, not prep outputs -> legal before the PDL wait)
    const float kr = sqrt_apx(__ldg(gamma + g) * 1.44269504088896f);
    const float mr = -__ldg(mu + g) * kr;

    // PDL: prep's writes (g_bfragH/L, g_dist) must be visible past here.
    asm volatile("griddepcontrol.wait;" ::: "memory");

    float acc[8];
    #pragma unroll
    for (int k = 0; k < 8; k++) acc[k] = 0.f;

    const int kb0 = warp * 96 + c;
    const uint4* bHp = g_bfragH + (warp * 6) * 32 + lane;
    const uint4* bLp = g_bfragL + (warp * 6) * 32 + lane;
    const float* dRow0 = g_dist + a0 * NPTS;
    const float* dRow1 = dRow0 + NPTS;

    #pragma unroll
    for (int s = 0; s < 6; s++) {
        const int kb = kb0 + s * 16;

        // B frags: 2 coalesced LDG.128 (L1-resident across CTAs)
        const uint4 bh = bHp[s * 32];
        const uint4 bl = bLp[s * 32];

        // distances: broadcast LDG.64 (4 distinct addresses per warp each)
        const float2 d00 = __ldg((const float2*)(dRow0 + kb));
        const float2 d01 = __ldg((const float2*)(dRow0 + kb + 8));
        const float2 d10 = __ldg((const float2*)(dRow1 + kb));
        const float2 d11 = __ldg((const float2*)(dRow1 + kb + 8));

        float v;
        v = fmaf(d00.x, kr, mr); const float e00x = ex2f(v * (-v));
        v = fmaf(d00.y, kr, mr); const float e00y = ex2f(v * (-v));
        v = fmaf(d10.x, kr, mr); const float e10x = ex2f(v * (-v));
        v = fmaf(d10.y, kr, mr); const float e10y = ex2f(v * (-v));
        v = fmaf(d01.x, kr, mr); const float e01x = ex2f(v * (-v));
        v = fmaf(d01.y, kr, mr); const float e01y = ex2f(v * (-v));
        v = fmaf(d11.x, kr, mr); const float e11x = ex2f(v * (-v));
        v = fmaf(d11.y, kr, mr); const float e11y = ex2f(v * (-v));

        const u32 ah0 = pack_bf16x2(e00x, e00y);
        const u32 ah1 = pack_bf16x2(e10x, e10y);
        const u32 ah2 = pack_bf16x2(e01x, e01y);
        const u32 ah3 = pack_bf16x2(e11x, e11y);

        const u32 al0 = pack_bf16x2(e00x - __uint_as_float(ah0 << 16),
                                    e00y - __uint_as_float(ah0 & 0xFFFF0000u));
        const u32 al1 = pack_bf16x2(e10x - __uint_as_float(ah1 << 16),
                                    e10y - __uint_as_float(ah1 & 0xFFFF0000u));
        const u32 al2 = pack_bf16x2(e01x - __uint_as_float(ah2 << 16),
                                    e01y - __uint_as_float(ah2 & 0xFFFF0000u));
        const u32 al3 = pack_bf16x2(e11x - __uint_as_float(ah3 << 16),
                                    e11y - __uint_as_float(ah3 & 0xFFFF0000u));

        mma16816(acc[0], acc[1], acc[2], acc[3], ah0, ah1, ah2, ah3, bh.x, bh.y);
        mma16816(acc[4], acc[5], acc[6], acc[7], ah0, ah1, ah2, ah3, bh.z, bh.w);
        mma16816(acc[0], acc[1], acc[2], acc[3], al0, al1, al2, al3, bh.x, bh.y);
        mma16816(acc[4], acc[5], acc[6], acc[7], al0, al1, al2, al3, bh.z, bh.w);
        mma16816(acc[0], acc[1], acc[2], acc[3], ah0, ah1, ah2, ah3, bl.x, bl.y);
        mma16816(acc[4], acc[5], acc[6], acc[7], ah0, ah1, ah2, ah3, bl.z, bl.w);
    }

    // ---- stash per-warp C tile: sRed[w][row][col] ----
    {
        float* rb = sRed + warp * 256;
        *(float2*)&rb[g * 16 + c]            = make_float2(acc[0], acc[1]);
        *(float2*)&rb[(g + 8) * 16 + c]      = make_float2(acc[2], acc[3]);
        *(float2*)&rb[g * 16 + 8 + c]        = make_float2(acc[4], acc[5]);
        *(float2*)&rb[(g + 8) * 16 + 8 + c]  = make_float2(acc[6], acc[7]);
    }
    __syncthreads();

    // ---- reduce over 8 warps ----
    {
        float s = 0.f;
        #pragma unroll
        for (int w = 0; w < 8; w++) s += sRed[w * 256 + tid];
        sG[tid] = s;
    }
    __syncthreads();

    // ---- W contraction: thread = (a_local, i, r); reduce r via shfl ----
    {
        const int r2 = tid & 7;
        const int i  = (tid >> 3) & 15;
        const int aL = tid >> 7;
        const float* gp = sG + (aL * 8 + r2) * 16;
        const float4* wp = (const float4*)W + r2 * 64 + i * 4;
        float a = 0.f;
        #pragma unroll
        for (int q = 0; q < 4; q++) {
            const float4 g4 = *(const float4*)(gp + q * 4);
            const float4 w4 = __ldg(wp + q);
            a = fmaf(w4.x, g4.x, a);
            a = fmaf(w4.y, g4.y, a);
            a = fmaf(w4.z, g4.z, a);
            a = fmaf(w4.w, g4.w, a);
        }
        a += __shfl_xor_sync(0xffffffffu, a, 1);
        a += __shfl_xor_sync(0xffffffffu, a, 2);
        a += __shfl_xor_sync(0xffffffffu, a, 4);
        if (r2 == 0) out[(a0 + aL) * 16 + i] = a * scale;
    }
}

// ---------------------------------------------------------------------------
extern "C" void kernel_launch(void* const* d_in, const int* in_sizes, int n_in,
                              void* d_out, int out_size)
{
    const float* feat  = (const float*)d_in[0];   // [1,768,16]
    const float* geom  = (const float*)d_in[1];   // [1,768,3]
    const float* W     = (const float*)d_in[2];   // [8,16,16]
    const float* mu    = (const float*)d_in[3];   // [8]
    const float* gamma = (const float*)d_in[4];   // [8]
    float* out = (float*)d_out;

    const int n_norm = in_sizes[1] / 3;
    const float scale = 1.0f / sqrtf((float)n_norm);

    conv_prep<<<6 + 288, NTHR>>>(feat, geom);     // B-frags + distance table

    // PDL launch: overlap conv_main's launch latency with prep.
    cudaLaunchConfig_t cfg = {};
    cfg.gridDim  = dim3(NTILES);
    cfg.blockDim = dim3(NTHR);
    cfg.dynamicSmemBytes = 0;
    cfg.stream = 0;
    cudaLaunchAttribute at[1];
    at[0].id = cudaLaunchAttributeProgrammaticStreamSerialization;
    at[0].val.programmaticStreamSerializationAllowed = 1;
    cfg.attrs = at;
    cfg.numAttrs = 1;
    cudaLaunchKernelEx(&cfg, conv_main, W, mu, gamma, scale, out);
}

// round 14
// speedup vs baseline: 1.0488x; 1.0488x over previous
#include <cuda_runtime.h>
#include <cuda_bf16.h>
#include <cstdint>

// Fixed shape: B=1, N=768, C_IN=C_OUT=16, R=8
#define NPTS   768
#define NTILES 384          // M-tiles of 16 rows (2 a's x 8 r); one CTA each
#define NTHR   256
#define NKS    48           // total ksteps (K=768 / 16)

typedef unsigned int u32;

// Built by conv_prep (all CTA-invariant):
__device__ uint4 g_bfragH[NKS * 32];     // B frags, mma-register order
__device__ uint4 g_bfragL[NKS * 32];
__device__ float g_dist[NPTS * NPTS];    // d[a][b], +EPS, sqrt'ed (2.36 MB)

__device__ __forceinline__ u32 pack_bf16x2(float lo, float hi) {
    u32 d;
    asm("cvt.rn.bf16x2.f32 %0, %1, %2;" : "=r"(d) : "f"(hi), "f"(lo));
    return d;
}
__device__ __forceinline__ float ex2f(float x) {
    float e;
    asm("ex2.approx.f32 %0, %1;" : "=f"(e) : "f"(x));
    return e;
}
__device__ __forceinline__ float sqrt_apx(float x) {
    float s;
    asm("sqrt.approx.f32 %0, %1;" : "=f"(s) : "f"(x));
    return s;
}
// D(16x8,f32) += A(16x16,row,bf16) * B(16x8,col,bf16)
__device__ __forceinline__ void mma16816(float& c0, float& c1, float& c2, float& c3,
                                         u32 a0, u32 a1, u32 a2, u32 a3,
                                         u32 b0, u32 b1) {
    asm("mma.sync.aligned.m16n8k16.row.col.f32.bf16.bf16.f32 "
        "{%0,%1,%2,%3}, {%4,%5,%6,%7}, {%8,%9}, {%0,%1,%2,%3};"
        : "+f"(c0), "+f"(c1), "+f"(c2), "+f"(c3)
        : "r"(a0), "r"(a1), "r"(a2), "r"(a3), "r"(b0), "r"(b1));
}

// ---------------------------------------------------------------------------
// Prep: blocks 0-5 build B fragments; blocks 6-293 build the distance table.
// Wide and parallel; runs under/before conv_main via PDL.
// ---------------------------------------------------------------------------
__global__ void __launch_bounds__(NTHR) conv_prep(const float* __restrict__ feat,
                                                  const float* __restrict__ geom)
{
    const int tid = threadIdx.x;

    if (blockIdx.x < 6) {
        // ---- B fragments in mma-register order ----
        const int idx  = blockIdx.x * NTHR + tid;         // 0..1535
        const int ks   = idx >> 5;
        const int lane = idx & 31;
        const int g    = lane >> 2;
        const int k0   = ks * 16 + (lane & 3) * 2;

        float f[8];
        #pragma unroll
        for (int q = 0; q < 2; q++) {                     // q=0: col g, q=1: col g+8
            const int j = g + q * 8;
            f[q * 4 + 0] = __ldg(&feat[(k0)     * 16 + j]);
            f[q * 4 + 1] = __ldg(&feat[(k0 + 1) * 16 + j]);
            f[q * 4 + 2] = __ldg(&feat[(k0 + 8) * 16 + j]);
            f[q * 4 + 3] = __ldg(&feat[(k0 + 9) * 16 + j]);
        }
        float h[8], l[8];
        #pragma unroll
        for (int q = 0; q < 8; q++) {
            h[q] = __bfloat162float(__float2bfloat16(f[q]));
            l[q] = f[q] - h[q];
        }
        uint4 BH, BL;
        BH.x = pack_bf16x2(h[0], h[1]);  BH.y = pack_bf16x2(h[2], h[3]);
        BH.z = pack_bf16x2(h[4], h[5]);  BH.w = pack_bf16x2(h[6], h[7]);
        BL.x = pack_bf16x2(l[0], l[1]);  BL.y = pack_bf16x2(l[2], l[3]);
        BL.z = pack_bf16x2(l[4], l[5]);  BL.w = pack_bf16x2(l[6], l[7]);
        g_bfragH[ks * 32 + lane] = BH;
        g_bfragL[ks * 32 + lane] = BL;
        return;
    }

    // ---- distance table: thread = (a, 8 consecutive b's) ----
    const int idx = (blockIdx.x - 6) * NTHR + tid;        // 0..73727
    const int a   = idx / 96;
    const int b8  = (idx % 96) * 8;

    const float ax = __ldg(&geom[a * 3]);
    const float ay = __ldg(&geom[a * 3 + 1]);
    const float az = __ldg(&geom[a * 3 + 2]);

    // 24 consecutive floats = geometry of b8..b8+7 (float4-aligned: 24*i % 4 == 0)
    float gb[24];
    const float4* gv = (const float4*)(geom + b8 * 3);
    #pragma unroll
    for (int q = 0; q < 6; q++) {
        const float4 v = __ldg(gv + q);
        gb[q * 4] = v.x; gb[q * 4 + 1] = v.y; gb[q * 4 + 2] = v.z; gb[q * 4 + 3] = v.w;
    }

    float d[8];
    #pragma unroll
    for (int q = 0; q < 8; q++) {
        const float dx = gb[q * 3]     - ax;
        const float dy = gb[q * 3 + 1] - ay;
        const float dz = gb[q * 3 + 2] - az;
        float d2 = fmaf(dx, dx, 1e-9f);
        d2 = fmaf(dy, dy, d2);
        d2 = fmaf(dz, dz, d2);
        d[q] = sqrt_apx(d2);
    }
    float4* dst = (float4*)(g_dist + a * NPTS + b8);
    dst[0] = make_float4(d[0], d[1], d[2], d[3]);
    dst[1] = make_float4(d[4], d[5], d[6], d[7]);
}

// ---------------------------------------------------------------------------
// Main (R10 topology, prologue removed):
//   CTA = M-tile of 16 rows (2 a's x 8 r); warp w covers K [w*96, w*96+96)
//   in 6 ksteps. Distances come from g_dist via broadcast LDG.64 (4 distinct
//   8B addresses per warp per vector). No distance prologue, no sD barrier.
// ---------------------------------------------------------------------------
__global__ void __launch_bounds__(NTHR, 4) conv_main(
    const float* __restrict__ W,       // [8,16,16]
    const float* __restrict__ mu,      // [8]
    const float* __restrict__ gamma,   // [8]
    float scale,
    float* __restrict__ out)           // [768,16]
{
    __shared__ float sRed[8 * 256];    // per-warp C tiles [w][row][col]
    __shared__ float sG[256];          // reduced G [row][col]

    const int tid  = threadIdx.x;
    const int lane = tid & 31;
    const int warp = tid >> 5;
    const int a0   = blockIdx.x * 2;

    const int g = lane >> 2;           // fragment group = r
    const int c = (lane & 3) * 2;

    // RBF consts (inputs, not prep outputs -> legal before the PDL wait)
    const float kr = sqrt_apx(__ldg(gamma + g) * 1.44269504088896f);
    const float mr = -__ldg(mu + g) * kr;

    // PDL: prep's writes (g_bfragH/L, g_dist) must be visible past here.
    asm volatile("griddepcontrol.wait;" ::: "memory");

    float acc[8];
    #pragma unroll
    for (int k = 0; k < 8; k++) acc[k] = 0.f;

    const int kb0 = warp * 96 + c;
    const uint4* bHp = g_bfragH + (warp * 6) * 32 + lane;
    const uint4* bLp = g_bfragL + (warp * 6) * 32 + lane;
    const float* dRow0 = g_dist + a0 * NPTS;
    const float* dRow1 = dRow0 + NPTS;

    #pragma unroll
    for (int s = 0; s < 6; s++) {
        const int kb = kb0 + s * 16;

        // B frags: 2 coalesced LDG.128 (L1-resident across CTAs)
        const uint4 bh = bHp[s * 32];
        const uint4 bl = bLp[s * 32];

        // distances: broadcast LDG.64 (4 distinct addresses per warp each)
        const float2 d00 = __ldg((const float2*)(dRow0 + kb));
        const float2 d01 = __ldg((const float2*)(dRow0 + kb + 8));
        const float2 d10 = __ldg((const float2*)(dRow1 + kb));
        const float2 d11 = __ldg((const float2*)(dRow1 + kb + 8));

        float v;
        v = fmaf(d00.x, kr, mr); const float e00x = ex2f(v * (-v));
        v = fmaf(d00.y, kr, mr); const float e00y = ex2f(v * (-v));
        v = fmaf(d10.x, kr, mr); const float e10x = ex2f(v * (-v));
        v = fmaf(d10.y, kr, mr); const float e10y = ex2f(v * (-v));
        v = fmaf(d01.x, kr, mr); const float e01x = ex2f(v * (-v));
        v = fmaf(d01.y, kr, mr); const float e01y = ex2f(v * (-v));
        v = fmaf(d11.x, kr, mr); const float e11x = ex2f(v * (-v));
        v = fmaf(d11.y, kr, mr); const float e11y = ex2f(v * (-v));

        const u32 ah0 = pack_bf16x2(e00x, e00y);
        const u32 ah1 = pack_bf16x2(e10x, e10y);
        const u32 ah2 = pack_bf16x2(e01x, e01y);
        const u32 ah3 = pack_bf16x2(e11x, e11y);

        const u32 al0 = pack_bf16x2(e00x - __uint_as_float(ah0 << 16),
                                    e00y - __uint_as_float(ah0 & 0xFFFF0000u));
        const u32 al1 = pack_bf16x2(e10x - __uint_as_float(ah1 << 16),
                                    e10y - __uint_as_float(ah1 & 0xFFFF0000u));
        const u32 al2 = pack_bf16x2(e01x - __uint_as_float(ah2 << 16),
                                    e01y - __uint_as_float(ah2 & 0xFFFF0000u));
        const u32 al3 = pack_bf16x2(e11x - __uint_as_float(ah3 << 16),
                                    e11y - __uint_as_float(ah3 & 0xFFFF0000u));

        mma16816(acc[0], acc[1], acc[2], acc[3], ah0, ah1, ah2, ah3, bh.x, bh.y);
        mma16816(acc[4], acc[5], acc[6], acc[7], ah0, ah1, ah2, ah3, bh.z, bh.w);
        mma16816(acc[0], acc[1], acc[2], acc[3], al0, al1, al2, al3, bh.x, bh.y);
        mma16816(acc[4], acc[5], acc[6], acc[7], al0, al1, al2, al3, bh.z, bh.w);
        mma16816(acc[0], acc[1], acc[2], acc[3], ah0, ah1, ah2, ah3, bl.x, bl.y);
        mma16816(acc[4], acc[5], acc[6], acc[7], ah0, ah1, ah2, ah3, bl.z, bl.w);
    }

    // ---- stash per-warp C tile: sRed[w][row][col] ----
    {
        float* rb = sRed + warp * 256;
        *(float2*)&rb[g * 16 + c]            = make_float2(acc[0], acc[1]);
        *(float2*)&rb[(g + 8) * 16 + c]      = make_float2(acc[2], acc[3]);
        *(float2*)&rb[g * 16 + 8 + c]        = make_float2(acc[4], acc[5]);
        *(float2*)&rb[(g + 8) * 16 + 8 + c]  = make_float2(acc[6], acc[7]);
    }
    __syncthreads();

    // ---- reduce over 8 warps ----
    {
        float s = 0.f;
        #pragma unroll
        for (int w = 0; w < 8; w++) s += sRed[w * 256 + tid];
        sG[tid] = s;
    }
    __syncthreads();

    // ---- W contraction: thread = (a_local, i, r); reduce r via shfl ----
    {
        const int r2 = tid & 7;
        const int i  = (tid >> 3) & 15;
        const int aL = tid >> 7;
        const float* gp = sG + (aL * 8 + r2) * 16;
        const float4* wp = (const float4*)W + r2 * 64 + i * 4;
        float a = 0.f;
        #pragma unroll
        for (int q = 0; q < 4; q++) {
            const float4 g4 = *(const float4*)(gp + q * 4);
            const float4 w4 = __ldg(wp + q);
            a = fmaf(w4.x, g4.x, a);
            a = fmaf(w4.y, g4.y, a);
            a = fmaf(w4.z, g4.z, a);
            a = fmaf(w4.w, g4.w, a);
        }
        a += __shfl_xor_sync(0xffffffffu, a, 1);
        a += __shfl_xor_sync(0xffffffffu, a, 2);
        a += __shfl_xor_sync(0xffffffffu, a, 4);
        if (r2 == 0) out[(a0 + aL) * 16 + i] = a * scale;
    }
}

// ---------------------------------------------------------------------------
extern "C" void kernel_launch(void* const* d_in, const int* in_sizes, int n_in,
                              void* d_out, int out_size)
{
    const float* feat  = (const float*)d_in[0];   // [1,768,16]
    const float* geom  = (const float*)d_in[1];   // [1,768,3]
    const float* W     = (const float*)d_in[2];   // [8,16,16]
    const float* mu    = (const float*)d_in[3];   // [8]
    const float* gamma = (const float*)d_in[4];   // [8]
    float* out = (float*)d_out;

    const int n_norm = in_sizes[1] / 3;
    const float scale = 1.0f / sqrtf((float)n_norm);

    conv_prep<<<6 + 288, NTHR>>>(feat, geom);     // B-frags + distance table

    // PDL launch: overlap conv_main's launch latency with prep.
    cudaLaunchConfig_t cfg = {};
    cfg.gridDim  = dim3(NTILES);
    cfg.blockDim = dim3(NTHR);
    cfg.dynamicSmemBytes = 0;
    cfg.stream = 0;
    cudaLaunchAttribute at[1];
    at[0].id = cudaLaunchAttributeProgrammaticStreamSerialization;
    at[0].val.programmaticStreamSerializationAllowed = 1;
    cfg.attrs = at;
    cfg.numAttrs = 1;
    cudaLaunchKernelEx(&cfg, conv_main, W, mu, gamma, scale, out);
}

// round 15
// speedup vs baseline: 1.2179x; 1.1612x over previous
#include <cuda_runtime.h>
#include <cuda_fp16.h>
#include <cstdint>

// Fixed shape: B=1, N=768, C_IN=C_OUT=16, R=8
#define NPTS   768
#define NTILES 384          // M-tiles of 16 rows (2 a's x 8 r); one CTA each
#define NTHR   256
#define NKS    48           // total ksteps (K=768 / 16)

typedef unsigned int u32;

// B fragments in mma-register order (fp16 hi + fp16 residual), by conv_prep:
//   g_bfragH[ks][lane] = {b00, b01, b10, b11} (uint4); identical for all CTAs.
__device__ uint4 g_bfragH[NKS * 32];
__device__ uint4 g_bfragL[NKS * 32];

__device__ __forceinline__ u32 pack_f16x2(float lo, float hi) {
    u32 d;
    asm("cvt.rn.f16x2.f32 %0, %1, %2;" : "=r"(d) : "f"(hi), "f"(lo));
    return d;
}
__device__ __forceinline__ float ex2f(float x) {
    float e;
    asm("ex2.approx.f32 %0, %1;" : "=f"(e) : "f"(x));
    return e;
}
__device__ __forceinline__ float sqrt_apx(float x) {
    float s;
    asm("sqrt.approx.f32 %0, %1;" : "=f"(s) : "f"(x));
    return s;
}
// D(16x8,f32) += A(16x16,row,f16) * B(16x8,col,f16)
__device__ __forceinline__ void mma16816(float& c0, float& c1, float& c2, float& c3,
                                         u32 a0, u32 a1, u32 a2, u32 a3,
                                         u32 b0, u32 b1) {
    asm("mma.sync.aligned.m16n8k16.row.col.f32.f16.f16.f32 "
        "{%0,%1,%2,%3}, {%4,%5,%6,%7}, {%8,%9}, {%0,%1,%2,%3};"
        : "+f"(c0), "+f"(c1), "+f"(c2), "+f"(c3)
        : "r"(a0), "r"(a1), "r"(a2), "r"(a3), "r"(b0), "r"(b1));
}

// ---------------------------------------------------------------------------
// Prep: build fp16 hi + fp16 residual B fragments in mma-fragment order.
// ---------------------------------------------------------------------------
__global__ void __launch_bounds__(NTHR) conv_prep(const float* __restrict__ feat)
{
    const int idx  = blockIdx.x * NTHR + threadIdx.x;     // 0..1535
    const int ks   = idx >> 5;
    const int lane = idx & 31;
    const int g    = lane >> 2;
    const int k0   = ks * 16 + (lane & 3) * 2;

    float f[8];
    #pragma unroll
    for (int q = 0; q < 2; q++) {                         // q=0: col g, q=1: col g+8
        const int j = g + q * 8;
        f[q * 4 + 0] = __ldg(&feat[(k0)     * 16 + j]);
        f[q * 4 + 1] = __ldg(&feat[(k0 + 1) * 16 + j]);
        f[q * 4 + 2] = __ldg(&feat[(k0 + 8) * 16 + j]);
        f[q * 4 + 3] = __ldg(&feat[(k0 + 9) * 16 + j]);
    }
    float h[8], l[8];
    #pragma unroll
    for (int q = 0; q < 8; q++) {
        h[q] = __half2float(__float2half_rn(f[q]));
        l[q] = f[q] - h[q];
    }
    uint4 BH, BL;
    BH.x = pack_f16x2(h[0], h[1]);  BH.y = pack_f16x2(h[2], h[3]);
    BH.z = pack_f16x2(h[4], h[5]);  BH.w = pack_f16x2(h[6], h[7]);
    BL.x = pack_f16x2(l[0], l[1]);  BL.y = pack_f16x2(l[2], l[3]);
    BL.z = pack_f16x2(l[4], l[5]);  BL.w = pack_f16x2(l[6], l[7]);
    g_bfragH[ks * 32 + lane] = BH;
    g_bfragL[ks * 32 + lane] = BL;
}

// ---------------------------------------------------------------------------
// Main (R10 topology, fp16 edition):
//   CTA = M-tile of 16 rows (2 a's x 8 r). Warp w covers K [w*96, w*96+96)
//   in 6 ksteps. A = rbf in SINGLE fp16 (no residual: fp16 rounding 4.9e-4
//   is the error budget); B = fp16 hi + residual -> 4 MMAs/kstep.
// ---------------------------------------------------------------------------
__global__ void __launch_bounds__(NTHR, 4) conv_main(
    const float* __restrict__ geom,    // [768,3]
    const float* __restrict__ W,       // [8,16,16]
    const float* __restrict__ mu,      // [8]
    const float* __restrict__ gamma,   // [8]
    float scale,
    float* __restrict__ out)           // [768,16]
{
    __shared__ float sD[2 * NPTS];     // distances d[a_local][b]
    __shared__ float sRed[8 * 256];    // per-warp C tiles [w][row][col]
    __shared__ float sG[256];          // reduced G [row][col]

    const int tid  = threadIdx.x;
    const int lane = tid & 31;
    const int warp = tid >> 5;
    const int a0   = blockIdx.x * 2;

    // ---- distances: 1536 values, 6 per thread ----
    {
        const float g0x = __ldg(&geom[a0 * 3]),       g0y = __ldg(&geom[a0 * 3 + 1]),
                    g0z = __ldg(&geom[a0 * 3 + 2]);
        const float g1x = __ldg(&geom[a0 * 3 + 3]),   g1y = __ldg(&geom[a0 * 3 + 4]),
                    g1z = __ldg(&geom[a0 * 3 + 5]);
        #pragma unroll
        for (int q = 0; q < 6; q++) {
            const int v  = tid + q * NTHR;            // 0..1535
            const int aL = v >= NPTS;
            const int b  = v - aL * NPTS;
            const float bx = __ldg(&geom[b * 3]);
            const float by = __ldg(&geom[b * 3 + 1]);
            const float bz = __ldg(&geom[b * 3 + 2]);
            const float dx = bx - (aL ? g1x : g0x);
            const float dy = by - (aL ? g1y : g0y);
            const float dz = bz - (aL ? g1z : g0z);
            float d2 = fmaf(dx, dx, 1e-9f);
            d2 = fmaf(dy, dy, d2);
            d2 = fmaf(dz, dz, d2);
            sD[v] = sqrt_apx(d2);
        }
    }
    __syncthreads();

    // PDL: prep's writes to g_bfragH/L must be visible past this point.
    asm volatile("griddepcontrol.wait;" ::: "memory");

    const int g = lane >> 2;           // fragment group = r
    const int c = (lane & 3) * 2;

    // RBF consts for this lane's r=g:  pw = -(kr*d + mr)^2
    const float kr = sqrt_apx(__ldg(gamma + g) * 1.44269504088896f);
    const float mr = -__ldg(mu + g) * kr;

    float acc[8];
    #pragma unroll
    for (int k = 0; k < 8; k++) acc[k] = 0.f;

    const int kb0 = warp * 96 + c;
    const uint4* bHp = g_bfragH + (warp * 6) * 32 + lane;
    const uint4* bLp = g_bfragL + (warp * 6) * 32 + lane;

    #pragma unroll
    for (int s = 0; s < 6; s++) {
        const int kb = kb0 + s * 16;

        // B frags: 2 coalesced LDG.128 (L1-resident; latency covered by occ)
        const uint4 bh = bHp[s * 32];
        const uint4 bl = bLp[s * 32];

        // ---- A fragments (rbf, single fp16) from smem distances ----
        const float2 d00 = *(const float2*)&sD[kb];            // row g   , cols c,c+1
        const float2 d01 = *(const float2*)&sD[kb + 8];        // row g   , cols c+8,c+9
        const float2 d10 = *(const float2*)&sD[NPTS + kb];     // row g+8
        const float2 d11 = *(const float2*)&sD[NPTS + kb + 8];

        float v;
        v = fmaf(d00.x, kr, mr); const float e00x = ex2f(v * (-v));
        v = fmaf(d00.y, kr, mr); const float e00y = ex2f(v * (-v));
        v = fmaf(d10.x, kr, mr); const float e10x = ex2f(v * (-v));
        v = fmaf(d10.y, kr, mr); const float e10y = ex2f(v * (-v));
        v = fmaf(d01.x, kr, mr); const float e01x = ex2f(v * (-v));
        v = fmaf(d01.y, kr, mr); const float e01y = ex2f(v * (-v));
        v = fmaf(d11.x, kr, mr); const float e11x = ex2f(v * (-v));
        v = fmaf(d11.y, kr, mr); const float e11y = ex2f(v * (-v));

        const u32 a0f = pack_f16x2(e00x, e00y);
        const u32 a1f = pack_f16x2(e10x, e10y);
        const u32 a2f = pack_f16x2(e01x, e01y);
        const u32 a3f = pack_f16x2(e11x, e11y);

        mma16816(acc[0], acc[1], acc[2], acc[3], a0f, a1f, a2f, a3f, bh.x, bh.y);
        mma16816(acc[4], acc[5], acc[6], acc[7], a0f, a1f, a2f, a3f, bh.z, bh.w);
        mma16816(acc[0], acc[1], acc[2], acc[3], a0f, a1f, a2f, a3f, bl.x, bl.y);
        mma16816(acc[4], acc[5], acc[6], acc[7], a0f, a1f, a2f, a3f, bl.z, bl.w);
    }

    // ---- stash per-warp C tile: sRed[w][row][col] ----
    {
        float* rb = sRed + warp * 256;
        *(float2*)&rb[g * 16 + c]            = make_float2(acc[0], acc[1]);
        *(float2*)&rb[(g + 8) * 16 + c]      = make_float2(acc[2], acc[3]);
        *(float2*)&rb[g * 16 + 8 + c]        = make_float2(acc[4], acc[5]);
        *(float2*)&rb[(g + 8) * 16 + 8 + c]  = make_float2(acc[6], acc[7]);
    }
    __syncthreads();

    // ---- reduce over 8 warps ----
    {
        float s = 0.f;
        #pragma unroll
        for (int w = 0; w < 8; w++) s += sRed[w * 256 + tid];
        sG[tid] = s;
    }
    __syncthreads();

    // ---- W contraction: thread = (a_local, i, r); reduce r via shfl ----
    {
        const int r2 = tid & 7;
        const int i  = (tid >> 3) & 15;
        const int aL = tid >> 7;
        const float* gp = sG + (aL * 8 + r2) * 16;
        const float4* wp = (const float4*)W + r2 * 64 + i * 4;
        float a = 0.f;
        #pragma unroll
        for (int q = 0; q < 4; q++) {
            const float4 g4 = *(const float4*)(gp + q * 4);
            const float4 w4 = __ldg(wp + q);
            a = fmaf(w4.x, g4.x, a);
            a = fmaf(w4.y, g4.y, a);
            a = fmaf(w4.z, g4.z, a);
            a = fmaf(w4.w, g4.w, a);
        }
        a += __shfl_xor_sync(0xffffffffu, a, 1);
        a += __shfl_xor_sync(0xffffffffu, a, 2);
        a += __shfl_xor_sync(0xffffffffu, a, 4);
        if (r2 == 0) out[(a0 + aL) * 16 + i] = a * scale;
    }
}

// ---------------------------------------------------------------------------
extern "C" void kernel_launch(void* const* d_in, const int* in_sizes, int n_in,
                              void* d_out, int out_size)
{
    const float* feat  = (const float*)d_in[0];   // [1,768,16]
    const float* geom  = (const float*)d_in[1];   // [1,768,3]
    const float* W     = (const float*)d_in[2];   // [8,16,16]
    const float* mu    = (const float*)d_in[3];   // [8]
    const float* gamma = (const float*)d_in[4];   // [8]
    float* out = (float*)d_out;

    const int n_norm = in_sizes[1] / 3;
    const float scale = 1.0f / sqrtf((float)n_norm);

    conv_prep<<<6, NTHR>>>(feat);

    // PDL launch: overlap conv_main's launch + distance prologue with prep.
    cudaLaunchConfig_t cfg = {};
    cfg.gridDim  = dim3(NTILES);
    cfg.blockDim = dim3(NTHR);
    cfg.dynamicSmemBytes = 0;
    cfg.stream = 0;
    cudaLaunchAttribute at[1];
    at[0].id = cudaLaunchAttributeProgrammaticStreamSerialization;
    at[0].val.programmaticStreamSerializationAllowed = 1;
    cfg.attrs = at;
    cfg.numAttrs = 1;
    cudaLaunchKernelEx(&cfg, conv_main, geom, W, mu, gamma, scale, out);
}